// round 5
// baseline (speedup 1.0000x reference)
#include <cuda_runtime.h>
#include <cstdint>

// CropAndResize: image (8,256,200,200) f32 NCHW, boxes (512,4) [y1,x1,y2,x2],
// box_indices (512,) int32 -> out (512,256,14,14) f32. Bilinear, extrap 0.
//
// R5: double-buffered SMEM staging of half-planes via cp.async.bulk + mbarrier.
// Block = (image, 4 channels); bulk loads stream sequentially (full DRAM bus
// efficiency) while 1024 threads gather the previously loaded half from SMEM.

#define IH 200
#define IW 200
#define CROP 14
#define NCH 256
#define NBOX 512
#define NIMG 8
#define PLANE (IH * IW)            // 40000
#define POS (CROP * CROP)          // 196
#define TPB 1024
#define MAXB 128
#define BOX_GRP 5                  // 5*196 = 980 worker threads
#define GCH 4                      // channels per block
#define NSTAGE (2 * GCH)
#define HROWS 101                  // buffer rows (covers y0=99,y1=100 pair)
#define BUF_BYTES (HROWS * IW * 4) // 80800
#define H0_BYTES (101 * IW * 4)    // rows 0..100
#define H1_BYTES (100 * IW * 4)    // rows 100..199

struct Tab { short i0, i1; float l; };   // 8 bytes

__device__ int d_perm[NBOX];
__device__ int d_img_off[NIMG + 1];
__device__ Tab d_ytab[NBOX * CROP];
__device__ Tab d_xtab[NBOX * CROP];
__device__ unsigned d_vy[NBOX];
__device__ unsigned d_vx[NBOX];

// Fused prep: counting-sort boxes by image + per-box interpolation tables.
__global__ __launch_bounds__(NBOX) void prep_kernel(
    const float* __restrict__ boxes,
    const int*   __restrict__ box_idx)
{
    __shared__ int cnt[NIMG];
    __shared__ int off[NIMG + 1];
    const int n = threadIdx.x;
    if (n < NIMG) cnt[n] = 0;
    __syncthreads();
    const int b = box_idx[n];
    atomicAdd(&cnt[b], 1);
    __syncthreads();
    if (n == 0) {
        int s = 0;
        for (int i = 0; i < NIMG; ++i) { off[i] = s; s += cnt[i]; }
        off[NIMG] = s;
    }
    __syncthreads();
    if (n <= NIMG) d_img_off[n] = off[n];
    __syncthreads();                      // d_img_off snapshot before mutation
    const int p = atomicAdd(&off[b], 1);  // bucket-internal order irrelevant
    d_perm[p] = n;

    // Interpolation tables for box n
    const float by1 = boxes[n * 4 + 0], bx1 = boxes[n * 4 + 1];
    const float by2 = boxes[n * 4 + 2], bx2 = boxes[n * 4 + 3];
    const float hs = (by2 - by1) * (float)(IH - 1) * (1.0f / (CROP - 1));
    const float ws = (bx2 - bx1) * (float)(IW - 1) * (1.0f / (CROP - 1));
    unsigned vy = 0, vx = 0;
    #pragma unroll
    for (int k = 0; k < CROP; ++k) {
        float v = by1 * (float)(IH - 1) + (float)k * hs;
        if (v >= 0.0f && v <= (float)(IH - 1)) vy |= (1u << k);
        float fl = floorf(v);
        Tab t;
        t.i0 = (short)(int)fminf(fmaxf(fl, 0.0f), (float)(IH - 1));
        t.i1 = (short)(int)fminf(fmaxf(ceilf(v), 0.0f), (float)(IH - 1));
        t.l  = v - fl;
        d_ytab[n * CROP + k] = t;

        v = bx1 * (float)(IW - 1) + (float)k * ws;
        if (v >= 0.0f && v <= (float)(IW - 1)) vx |= (1u << k);
        fl = floorf(v);
        t.i0 = (short)(int)fminf(fmaxf(fl, 0.0f), (float)(IW - 1));
        t.i1 = (short)(int)fminf(fmaxf(ceilf(v), 0.0f), (float)(IW - 1));
        t.l  = v - fl;
        d_xtab[n * CROP + k] = t;
    }
    d_vy[n] = vy;
    d_vx[n] = vx;
}

// Dynamic smem layout
#define SM_BUF0   0
#define SM_BUF1   BUF_BYTES
#define SM_MBAR   (2 * BUF_BYTES)                  // 2 x 8B, 16B aligned
#define SM_YTAB   (SM_MBAR + 16)
#define SM_XTAB   (SM_YTAB + MAXB * CROP * 8)
#define SM_NLIST  (SM_XTAB + MAXB * CROP * 8)
#define SM_VY     (SM_NLIST + MAXB * 4)
#define SM_VX     (SM_VY + MAXB * 4)
#define SM_TOTAL  (SM_VX + MAXB * 4)               // 191,824 bytes

__device__ __forceinline__ void mbar_wait(uint32_t addr, int parity)
{
    asm volatile(
        "{\n\t.reg .pred P;\n"
        "W%=:\n\t"
        "mbarrier.try_wait.parity.shared.b64 P, [%0], %1;\n\t"
        "@P bra D%=;\n\t"
        "bra W%=;\n"
        "D%=:\n\t}"
        :: "r"(addr), "r"(parity) : "memory");
}

__global__ __launch_bounds__(TPB, 1) void crop_resize_kernel(
    const float* __restrict__ image,
    float*       __restrict__ out)
{
    extern __shared__ char smem[];
    float* buf0 = (float*)(smem + SM_BUF0);
    float* buf1 = (float*)(smem + SM_BUF1);
    Tab*      ytab  = (Tab*)(smem + SM_YTAB);
    Tab*      xtab  = (Tab*)(smem + SM_XTAB);
    int*      nlist = (int*)(smem + SM_NLIST);
    unsigned* vys   = (unsigned*)(smem + SM_VY);
    unsigned* vxs   = (unsigned*)(smem + SM_VX);

    const uint32_t mbar_s = (uint32_t)__cvta_generic_to_shared(smem + SM_MBAR);
    const uint32_t buf_s  = (uint32_t)__cvta_generic_to_shared(smem);

    const int img = blockIdx.x / (NCH / GCH);
    const int cg  = (blockIdx.x % (NCH / GCH)) * GCH;
    const int tid = threadIdx.x;
    const float* planes = image + ((size_t)img * NCH + cg) * PLANE;

    if (tid == 0) {
        asm volatile("mbarrier.init.shared.b64 [%0], %1;" :: "r"(mbar_s),     "r"(1));
        asm volatile("mbarrier.init.shared.b64 [%0], %1;" :: "r"(mbar_s + 8), "r"(1));
    }
    __syncthreads();

    // Issue a half-plane bulk load for stage s (channel s>>1, half s&1).
    auto issue = [&](int s) {
        const int c = s >> 1, h = s & 1;
        const uint32_t bytes = h ? H1_BYTES : H0_BYTES;
        const uint32_t dst   = buf_s + (h ? SM_BUF1 : SM_BUF0);
        const uint32_t mb    = mbar_s + 8 * h;
        const float* src = planes + (size_t)c * PLANE + (size_t)h * 100 * IW;
        asm volatile("mbarrier.arrive.expect_tx.shared.b64 _, [%0], %1;"
                     :: "r"(mb), "r"(bytes) : "memory");
        asm volatile(
            "cp.async.bulk.shared::cta.global.mbarrier::complete_tx::bytes "
            "[%0], [%1], %2, [%3];"
            :: "r"(dst), "l"(src), "r"(bytes), "r"(mb) : "memory");
    };

    if (tid == 0) { issue(0); issue(1); }   // prime depth-2 pipeline

    const int o0 = d_img_off[img];
    const int o1 = d_img_off[img + 1];

    // Fixed per-thread decode: myb in [0,5), pos in [0,196)
    const int myb = tid / POS;
    const int pos = tid - myb * POS;
    const int r   = pos / CROP;
    const int col = pos - r * CROP;
    const bool worker = (tid < BOX_GRP * POS);
    float* outc_base = out + (size_t)cg * POS + pos;

    int ph0 = 0, ph1 = 0;
    for (int s = 0; s < NSTAGE; ++s) {
        const int h = s & 1;
        const int c = s >> 1;

        // Wait for this stage's half-plane
        if (h == 0) { mbar_wait(mbar_s,     ph0); ph0 ^= 1; }
        else        { mbar_wait(mbar_s + 8, ph1); ph1 ^= 1; }

        // pl + y*IW is valid for y inside this half
        const float* pl = (h ? (buf1 - 100 * IW) : buf0);
        float* outc = outc_base + (size_t)c * POS;

        for (int done = o0; done < o1; done += MAXB) {
            const int pb = min(o1 - done, MAXB);

            __syncthreads();   // protect tables from previous readers
            if (tid < pb) {
                const int n = d_perm[done + tid];
                nlist[tid] = n;
                vys[tid] = d_vy[n];
                vxs[tid] = d_vx[n];
            }
            __syncthreads();
            for (int t = tid; t < pb * CROP; t += TPB) {
                const int bl = t / CROP;
                const int e  = t - bl * CROP;
                const int n  = nlist[bl];
                ytab[t] = d_ytab[n * CROP + e];
                xtab[t] = d_xtab[n * CROP + e];
            }
            __syncthreads();

            for (int base = 0; base < pb; base += BOX_GRP) {
                const int bl = base + myb;
                if (worker && bl < pb) {
                    const Tab ty = ytab[bl * CROP + r];
                    if ((((int)ty.i0 >= 100) ? 1 : 0) == h) {
                        const Tab tx = xtab[bl * CROP + col];
                        const unsigned v = (vys[bl] >> r) & (vxs[bl] >> col) & 1u;
                        const float* p0 = pl + (int)ty.i0 * IW;
                        const float* p1 = pl + (int)ty.i1 * IW;
                        const float tl  = p0[tx.i0];
                        const float tr  = p0[tx.i1];
                        const float blv = p1[tx.i0];
                        const float br  = p1[tx.i1];
                        const float top = fmaf(tr - tl,  tx.l, tl);
                        const float bot = fmaf(br - blv, tx.l, blv);
                        float val = fmaf(bot - top, ty.l, top);
                        if (!v) val = 0.0f;
                        __stcs(outc + (size_t)nlist[bl] * (NCH * POS), val);
                    }
                }
            }
        }

        __syncthreads();   // all gathers on buf[h] done -> safe to overwrite
        if (s + 2 < NSTAGE && tid == 0) {
            asm volatile("fence.proxy.async.shared::cta;" ::: "memory");
            issue(s + 2);
        }
    }
}

extern "C" void kernel_launch(void* const* d_in, const int* in_sizes, int n_in,
                              void* d_out, int out_size)
{
    const float* image   = (const float*)d_in[0];
    const float* boxes   = (const float*)d_in[1];
    const int*   box_idx = (const int*)d_in[2];
    float*       out     = (float*)d_out;

    static bool attr_set = false;
    if (!attr_set) {
        cudaFuncSetAttribute(crop_resize_kernel,
                             cudaFuncAttributeMaxDynamicSharedMemorySize,
                             SM_TOTAL);
        attr_set = true;
    }

    prep_kernel<<<1, NBOX>>>(boxes, box_idx);
    crop_resize_kernel<<<NIMG * (NCH / GCH), TPB, SM_TOTAL>>>(image, out);
}

// round 6
// speedup vs baseline: 1.3248x; 1.3248x over previous
#include <cuda_runtime.h>
#include <cstdint>

// CropAndResize: image (8,256,200,200) f32 NCHW, boxes (512,4) [y1,x1,y2,x2],
// box_indices (512,) int32 -> out (512,256,14,14) f32. Bilinear, extrap 0.
//
// R6: single kernel. Block = (image, channel, half-plane). cp.async stages the
// half-plane sequentially into bank-conflict-padded SMEM (each image byte read
// once chip-wide); 2 CTAs/SM overlap one block's loads with the other's SMEM
// gathers. Tables built in-block from boxes/box_idx (L2-hot).

#define IH 200
#define IW 200
#define CROP 14
#define NCH 256
#define NBOX 512
#define NIMG 8
#define PLANE (IH * IW)
#define POS (CROP * CROP)        // 196
#define PITCH 204                // smem row pitch in floats (816B: 16B-aligned, odd-ish bank stride)
#define MAXB 96                  // boxes per table chunk (mean 64, ~4.3 sigma headroom + fallback loop)
#define TPB 640
#define BOX_GRP 3                // 3*196 = 588 worker threads
#define CPR 50                   // 16B chunks per image row (200*4/16)

// Dynamic smem layout (bytes)
#define BUF_BYTES (101 * PITCH * 4)                 // 82416
#define SM_YTAB   BUF_BYTES                         // MAXB*CROP*8
#define SM_XTAB   (SM_YTAB + MAXB * CROP * 8)
#define SM_NLIST  (SM_XTAB + MAXB * CROP * 8)       // NBOX ints
#define SM_VM     (SM_NLIST + NBOX * 4)             // MAXB u32
#define SM_CNT    (SM_VM + MAXB * 4)
#define SM_TOTAL  (SM_CNT + 16)                     // ~106.4 KB -> 2 CTAs/SM

__global__ __launch_bounds__(TPB, 2) void crop_resize_kernel(
    const float* __restrict__ image,
    const float* __restrict__ boxes,
    const int*   __restrict__ box_idx,
    float*       __restrict__ out)
{
    extern __shared__ char smem[];
    float*    plane = (float*)smem;
    uint2*    ytab  = (uint2*)(smem + SM_YTAB);
    uint2*    xtab  = (uint2*)(smem + SM_XTAB);
    int*      nlist = (int*)(smem + SM_NLIST);
    unsigned* vm    = (unsigned*)(smem + SM_VM);
    int*      cnt   = (int*)(smem + SM_CNT);

    const int bx  = blockIdx.x;
    const int img = bx >> 9;
    const int ch  = (bx & 511) >> 1;
    const int h   = bx & 1;
    const int tid = threadIdx.x;

    // ---- Stage half-plane: sequential 16B cp.async into padded buffer ----
    // half 0: image rows 0..100 (101 rows, includes row 100 as y1 target)
    // half 1: image rows 100..199 (100 rows)
    const int nrows  = h ? 100 : 101;
    const int nchunk = nrows * CPR;
    const char* srcb = (const char*)(image + ((size_t)img * NCH + ch) * PLANE
                                           + (size_t)h * 100 * IW);
    const uint32_t smem_b = (uint32_t)__cvta_generic_to_shared(smem);
    for (int i = tid; i < nchunk; i += TPB) {
        const int row = i / CPR;
        const int c16 = i - row * CPR;
        const uint32_t dst = smem_b + row * (PITCH * 4) + c16 * 16;
        const char*    src = srcb + row * (IW * 4) + c16 * 16;
        asm volatile("cp.async.cg.shared.global [%0], [%1], 16;"
                     :: "r"(dst), "l"(src));
    }
    asm volatile("cp.async.commit_group;");

    // ---- Filter boxes of this image (runs while copies are in flight) ----
    if (tid == 0) *cnt = 0;
    __syncthreads();
    if (tid < NBOX && box_idx[tid] == img)
        nlist[atomicAdd(cnt, 1)] = tid;
    __syncthreads();
    const int nb = *cnt;

    asm volatile("cp.async.wait_group 0;");
    __syncthreads();   // all copies visible to all threads

    // ---- Fixed per-thread gather decode ----
    const int myb = tid / POS;               // 0..2 workers, 3 = idle
    const int pos = tid - myb * POS;
    const int r   = pos / CROP;
    const int col = pos - r * CROP;
    const bool worker = (myb < BOX_GRP);
    float* outp = out + (size_t)ch * POS + pos;

    for (int b0 = 0; b0 < nb; b0 += MAXB) {
        const int pb = min(nb - b0, MAXB);

        __syncthreads();                 // protect tables from previous readers
        if (tid < MAXB) vm[tid] = 0;
        __syncthreads();

        // Build compressed tables for boxes nlist[b0 .. b0+pb)
        for (int t = tid; t < pb * CROP; t += TPB) {
            const int bs = t / CROP;
            const int e  = t - bs * CROP;
            const float4 bq = ((const float4*)boxes)[nlist[b0 + bs]]; // y1,x1,y2,x2

            // y axis: store in-half row offsets o0,o1 (shorts) + fraction
            {
                const float sc = (bq.z - bq.x) * (float)(IH - 1) * (1.0f / (CROP - 1));
                const float v  = bq.x * (float)(IH - 1) + (float)e * sc;
                const float fl = floorf(v);
                const int y0 = (int)fminf(fmaxf(fl, 0.0f), (float)(IH - 1));
                const int o0 = y0 - 100 * h;
                const int o1 = min(y0 + 1, IH - 1) - 100 * h;
                ytab[bs * CROP + e] = make_uint2(
                    (unsigned)(o0 & 0xFFFF) | ((unsigned)(o1 & 0xFFFF) << 16),
                    __float_as_uint(v - fl));
                if (v >= 0.0f && v <= (float)(IH - 1))
                    atomicOr(&vm[bs], 1u << e);
            }
            // x axis: x0, x1=min(x0+1,199) + fraction
            {
                const float sc = (bq.w - bq.y) * (float)(IW - 1) * (1.0f / (CROP - 1));
                const float v  = bq.y * (float)(IW - 1) + (float)e * sc;
                const float fl = floorf(v);
                const int x0 = (int)fminf(fmaxf(fl, 0.0f), (float)(IW - 1));
                const int x1 = min(x0 + 1, IW - 1);
                xtab[bs * CROP + e] = make_uint2(
                    (unsigned)x0 | ((unsigned)x1 << 16),
                    __float_as_uint(v - fl));
                if (v >= 0.0f && v <= (float)(IW - 1))
                    atomicOr(&vm[bs], 1u << (16 + e));
            }
        }
        __syncthreads();

        // Gather: thread owns (myb, pos); rows partitioned by half via o0.
        if (worker) {
            for (int s = 0; s < pb; s += BOX_GRP) {
                const int b = s + myb;
                if (b < pb) {
                    const uint2 ty = ytab[b * CROP + r];
                    const int o0 = (int)(short)(ty.x & 0xFFFF);
                    if ((unsigned)o0 < 100u) {       // this half owns the row
                        const int o1 = (int)(short)(ty.x >> 16);
                        const float ly = __uint_as_float(ty.y);
                        const uint2 tx = xtab[b * CROP + col];
                        const int x0 = tx.x & 0xFFFF;
                        const int x1 = tx.x >> 16;
                        const float lx = __uint_as_float(tx.y);
                        const float* r0 = plane + o0 * PITCH;
                        const float* r1 = plane + o1 * PITCH;
                        const float tl  = r0[x0];
                        const float tr  = r0[x1];
                        const float blv = r1[x0];
                        const float br  = r1[x1];
                        const float top = fmaf(tr - tl,  lx, tl);
                        const float bot = fmaf(br - blv, lx, blv);
                        float val = fmaf(bot - top, ly, top);
                        const unsigned m = vm[b];
                        if (!((m >> r) & (m >> (16 + col)) & 1u)) val = 0.0f;
                        __stcs(outp + (size_t)nlist[b0 + b] * (NCH * POS), val);
                    }
                }
            }
        }
    }
}

extern "C" void kernel_launch(void* const* d_in, const int* in_sizes, int n_in,
                              void* d_out, int out_size)
{
    const float* image   = (const float*)d_in[0];
    const float* boxes   = (const float*)d_in[1];
    const int*   box_idx = (const int*)d_in[2];
    float*       out     = (float*)d_out;

    static bool attr_set = false;
    if (!attr_set) {
        cudaFuncSetAttribute(crop_resize_kernel,
                             cudaFuncAttributeMaxDynamicSharedMemorySize,
                             SM_TOTAL);
        attr_set = true;
    }

    crop_resize_kernel<<<NIMG * NCH * 2, TPB, SM_TOTAL>>>(image, boxes, box_idx, out);
}

// round 7
// speedup vs baseline: 1.3426x; 1.0134x over previous
#include <cuda_runtime.h>
#include <cstdint>

// CropAndResize: image (8,256,200,200) f32 NCHW, boxes (512,4) [y1,x1,y2,x2],
// box_indices (512,) int32 -> out (512,256,14,14) f32. Bilinear, extrap 0.
//
// R7: prep kernel builds permuted compressed tables ONCE; main blocks
// (image, channel, half-plane) stream the half-plane via cp.async into padded
// SMEM and gather with table lookups only (no per-block table math).

#define IH 200
#define IW 200
#define CROP 14
#define NCH 256
#define NBOX 512
#define NIMG 8
#define PLANE (IH * IW)
#define POS (CROP * CROP)        // 196
#define PITCH 204                // smem row pitch (floats); 816B rows, 16B aligned
#define MAXB 112                 // boxes per table chunk (mean 64/image)
#define TPB 640
#define BOX_GRP 3                // 3*196 = 588 worker threads
#define CPR 50                   // 16B chunks per image row

__device__ int   d_img_off[NIMG + 1];
__device__ int   d_nid[NBOX];            // slot -> original box id
__device__ uint2 d_ytab[NBOX * CROP];    // x: y0 | dy<<8 | vy<<9 ; y: ly bits
__device__ uint2 d_xtab[NBOX * CROP];    // x: x0 | vx<<8           ; y: lx bits

__global__ __launch_bounds__(NBOX) void prep_kernel(
    const float* __restrict__ boxes,
    const int*   __restrict__ box_idx)
{
    __shared__ int cnt[NIMG];
    __shared__ int off[NIMG + 1];
    const int n = threadIdx.x;
    if (n < NIMG) cnt[n] = 0;
    __syncthreads();
    const int b = box_idx[n];
    atomicAdd(&cnt[b], 1);
    __syncthreads();
    if (n == 0) {
        int s = 0;
        for (int i = 0; i < NIMG; ++i) { off[i] = s; s += cnt[i]; }
        off[NIMG] = s;
    }
    __syncthreads();
    if (n <= NIMG) d_img_off[n] = off[n];
    __syncthreads();                      // snapshot before mutation
    const int p = atomicAdd(&off[b], 1);  // bucket-internal order irrelevant
    d_nid[p] = n;

    const float4 bq = ((const float4*)boxes)[n];   // y1,x1,y2,x2
    const float ys = (bq.z - bq.x) * (float)(IH - 1) * (1.0f / (CROP - 1));
    const float xs = (bq.w - bq.y) * (float)(IW - 1) * (1.0f / (CROP - 1));
    #pragma unroll
    for (int k = 0; k < CROP; ++k) {
        {
            const float v  = bq.x * (float)(IH - 1) + (float)k * ys;
            const float fl = floorf(v);
            const int y0 = (int)fminf(fmaxf(fl, 0.0f), (float)(IH - 1));
            const unsigned dy = (y0 < IH - 1) ? 1u : 0u;
            const unsigned vy = (v >= 0.0f && v <= (float)(IH - 1)) ? 1u : 0u;
            d_ytab[p * CROP + k] = make_uint2(
                (unsigned)y0 | (dy << 8) | (vy << 9), __float_as_uint(v - fl));
        }
        {
            const float v  = bq.y * (float)(IW - 1) + (float)k * xs;
            const float fl = floorf(v);
            const int x0 = (int)fminf(fmaxf(fl, 0.0f), (float)(IW - 1));
            const unsigned vx = (v >= 0.0f && v <= (float)(IW - 1)) ? 1u : 0u;
            d_xtab[p * CROP + k] = make_uint2(
                (unsigned)x0 | (vx << 8), __float_as_uint(v - fl));
        }
    }
}

// Dynamic smem layout (bytes)
#define BUF_BYTES (101 * PITCH * 4)                 // 82416
#define SM_YTAB   BUF_BYTES
#define SM_XTAB   (SM_YTAB + MAXB * CROP * 8)
#define SM_NID    (SM_XTAB + MAXB * CROP * 8)
#define SM_TOTAL  (SM_NID + MAXB * 4)               // ~108 KB -> 2 CTAs/SM

__global__ __launch_bounds__(TPB, 2) void crop_resize_kernel(
    const float* __restrict__ image,
    float*       __restrict__ out)
{
    extern __shared__ char smem[];
    float* plane = (float*)smem;
    uint2* ytab  = (uint2*)(smem + SM_YTAB);
    uint2* xtab  = (uint2*)(smem + SM_XTAB);
    int*   nid   = (int*)(smem + SM_NID);

    const int bx  = blockIdx.x;
    const int img = bx >> 9;
    const int ch  = (bx & 511) >> 1;
    const int h   = bx & 1;
    const int tid = threadIdx.x;
    const int hh  = 100 * h;

    // ---- Stage half-plane: sequential 16B cp.async into padded buffer ----
    // half 0: image rows 0..100 (101 rows, row 100 needed as y1 partner)
    // half 1: image rows 100..199 (100 rows)
    const int nrows  = h ? 100 : 101;
    const int nchunk = nrows * CPR;
    const char* srcb = (const char*)(image + ((size_t)img * NCH + ch) * PLANE
                                           + (size_t)hh * IW);
    const uint32_t smem_b = (uint32_t)__cvta_generic_to_shared(smem);
    #pragma unroll 4
    for (int i = tid; i < nchunk; i += TPB) {
        const int row = i / CPR;
        const int c16 = i - row * CPR;
        asm volatile("cp.async.cg.shared.global [%0], [%1], 16;"
                     :: "r"(smem_b + row * (PITCH * 4) + c16 * 16),
                        "l"(srcb + row * (IW * 4) + c16 * 16));
    }
    asm volatile("cp.async.commit_group;");

    // Zero the 4 pad floats of each row (makes x0=199 float-pair reads safe).
    if (tid < 101) {
        float4* pad = (float4*)(smem + tid * (PITCH * 4) + IW * 4);
        *pad = make_float4(0.f, 0.f, 0.f, 0.f);
    }

    const int o0 = d_img_off[img];
    const int nb = d_img_off[img + 1] - o0;

    // Fixed per-thread decode
    const int myb = tid / POS;
    const int pos = tid - myb * POS;
    const int r   = pos / CROP;
    const int col = pos - r * CROP;
    const bool worker = (myb < BOX_GRP);
    float* outp = out + (size_t)ch * POS + pos;

    for (int b0 = 0; b0 < nb; b0 += MAXB) {
        const int pb = min(nb - b0, MAXB);

        __syncthreads();                  // protect smem tables from readers
        for (int t = tid; t < pb * CROP; t += TPB) {
            ytab[t] = d_ytab[(o0 + b0) * CROP + t];
            xtab[t] = d_xtab[(o0 + b0) * CROP + t];
        }
        if (tid < pb) nid[tid] = d_nid[o0 + b0 + tid];

        if (b0 == 0) asm volatile("cp.async.wait_group 0;");
        __syncthreads();

        if (worker) {
            for (int s = 0; s < pb; s += BOX_GRP) {
                const int b = s + myb;
                if (b < pb) {
                    const uint2 ty = ytab[b * CROP + r];
                    const int o = (int)(ty.x & 0xFF) - hh;
                    if ((unsigned)o < 100u) {          // this half owns the row
                        const uint2 tx = xtab[b * CROP + col];
                        const int x0 = tx.x & 0xFF;
                        const float* r0 = plane + o * PITCH + x0;
                        const float* r1 = r0 + ((ty.x >> 8) & 1u) * PITCH;
                        const float tl = r0[0], tr = r0[1];
                        const float bl = r1[0], br = r1[1];
                        const float lx = __uint_as_float(tx.y);
                        const float ly = __uint_as_float(ty.y);
                        const float top = fmaf(tr - tl, lx, tl);
                        const float bot = fmaf(br - bl, lx, bl);
                        float val = fmaf(bot - top, ly, top);
                        if (!((ty.x >> 9) & (tx.x >> 8) & 1u)) val = 0.0f;
                        __stcs(outp + (size_t)nid[b] * (NCH * POS), val);
                    }
                }
            }
        }
    }
}

extern "C" void kernel_launch(void* const* d_in, const int* in_sizes, int n_in,
                              void* d_out, int out_size)
{
    const float* image   = (const float*)d_in[0];
    const float* boxes   = (const float*)d_in[1];
    const int*   box_idx = (const int*)d_in[2];
    float*       out     = (float*)d_out;

    static bool attr_set = false;
    if (!attr_set) {
        cudaFuncSetAttribute(crop_resize_kernel,
                             cudaFuncAttributeMaxDynamicSharedMemorySize,
                             SM_TOTAL);
        attr_set = true;
    }

    prep_kernel<<<1, NBOX>>>(boxes, box_idx);
    crop_resize_kernel<<<NIMG * NCH * 2, TPB, SM_TOTAL>>>(image, out);
}

// round 8
// speedup vs baseline: 1.4188x; 1.0568x over previous
#include <cuda_runtime.h>
#include <cstdint>

// CropAndResize: image (8,256,200,200) f32 NCHW, boxes (512,4) [y1,x1,y2,x2],
// box_indices (512,) int32 -> out (512,256,14,14) f32. Bilinear, extrap 0.
//
// R8: prep builds per-(image,half) compacted (box,row) entry lists + per-box
// x-tables. Main block = (image, channel, half): cp.async streams the padded
// half-plane while tables copy; gather loop has zero wasted iterations.

#define IH 200
#define IW 200
#define CROP 14
#define NCH 256
#define NBOX 512
#define NIMG 8
#define PLANE (IH * IW)
#define POS (CROP * CROP)          // 196
#define PITCH 204                  // smem row pitch (floats), 816B rows
#define MAXBI 128                  // max boxes per image (mean 64, +8.5 sigma)
#define MAXE (MAXBI * CROP)        // max entries per (image,half)
#define TPB 896                    // 64 entry-groups x 14 cols, no idle lanes
#define EGRP (TPB / CROP)          // 64
#define CPR 50                     // 16B chunks per image row

__device__ int   d_nbox[NIMG];            // boxes per image
__device__ int   d_nent[NIMG * 2];        // entries per (image, half)
__device__ uint2 d_xtab[NIMG * MAXBI * CROP];  // {x0 | vx<<8, lx}
__device__ uint2 d_ent[NIMG * 2 * MAXE];  // {nid|slot<<9|o<<17|dy<<24|vy<<25|r<<26, ly}

__global__ __launch_bounds__(NBOX) void prep_kernel(
    const float* __restrict__ boxes,
    const int*   __restrict__ box_idx)
{
    const int n = threadIdx.x;
    if (n < NIMG) d_nbox[n] = 0;
    if (n < NIMG * 2) d_nent[n] = 0;
    __syncthreads();                 // single block: atomics below are coherent

    const int img  = box_idx[n];
    const int slot = atomicAdd(&d_nbox[img], 1);   // order irrelevant
    const float4 bq = ((const float4*)boxes)[n];   // y1,x1,y2,x2
    const float ys = (bq.z - bq.x) * (float)(IH - 1) * (1.0f / (CROP - 1));
    const float xs = (bq.w - bq.y) * (float)(IW - 1) * (1.0f / (CROP - 1));

    #pragma unroll
    for (int k = 0; k < CROP; ++k) {
        // x table entry (per box, per crop-col)
        {
            const float v  = bq.y * (float)(IW - 1) + (float)k * xs;
            const float fl = floorf(v);
            const int x0 = (int)fminf(fmaxf(fl, 0.0f), (float)(IW - 1));
            const unsigned vx = (v >= 0.0f && v <= (float)(IW - 1)) ? 1u : 0u;
            d_xtab[(img * MAXBI + slot) * CROP + k] =
                make_uint2((unsigned)x0 | (vx << 8), __float_as_uint(v - fl));
        }
        // y row -> entry in owning half's work list
        {
            const float v  = bq.x * (float)(IH - 1) + (float)k * ys;
            const float fl = floorf(v);
            const int y0 = (int)fminf(fmaxf(fl, 0.0f), (float)(IH - 1));
            const int h  = (y0 >= 100) ? 1 : 0;
            const int o  = y0 - 100 * h;                 // 0..100
            const unsigned dy = (y0 < IH - 1) ? 1u : 0u;
            const unsigned vy = (v >= 0.0f && v <= (float)(IH - 1)) ? 1u : 0u;
            const int idx = atomicAdd(&d_nent[img * 2 + h], 1);
            d_ent[(img * 2 + h) * MAXE + idx] = make_uint2(
                (unsigned)n | ((unsigned)slot << 9) | ((unsigned)o << 17)
                | (dy << 24) | (vy << 25) | ((unsigned)k << 26),
                __float_as_uint(v - fl));
        }
    }
}

// Dynamic smem layout (bytes)
#define BUF_BYTES (101 * PITCH * 4)                  // 82416
#define SM_XTAB   BUF_BYTES                          // MAXBI*CROP*8 = 14336
#define SM_ENT    (SM_XTAB + MAXBI * CROP * 8)       // MAXE*8 = 14336
#define SM_TOTAL  (SM_ENT + MAXE * 8)                // 111088 -> 2 CTAs/SM

__global__ __launch_bounds__(TPB, 2) void crop_resize_kernel(
    const float* __restrict__ image,
    float*       __restrict__ out)
{
    extern __shared__ char smem[];
    float* plane = (float*)smem;
    uint2* xtab  = (uint2*)(smem + SM_XTAB);
    uint2* ents  = (uint2*)(smem + SM_ENT);

    const int bx  = blockIdx.x;
    const int img = bx >> 9;
    const int ch  = (bx & 511) >> 1;
    const int h   = bx & 1;
    const int tid = threadIdx.x;

    // ---- Stage half-plane: sequential 16B cp.async into padded buffer ----
    // half 0: rows 0..100 (101 rows; row 100 is y1 partner of y0=99)
    // half 1: rows 100..199 (100 rows)
    const int nchunk = (h ? 100 : 101) * CPR;
    const char* srcb = (const char*)(image + ((size_t)img * NCH + ch) * PLANE
                                           + (size_t)(100 * h) * IW);
    const uint32_t smem_b = (uint32_t)__cvta_generic_to_shared(smem);
    #pragma unroll 3
    for (int i = tid; i < nchunk; i += TPB) {
        const int row = i / CPR;
        const int c16 = i - row * CPR;
        asm volatile("cp.async.cg.shared.global [%0], [%1], 16;"
                     :: "r"(smem_b + row * (PITCH * 4) + c16 * 16),
                        "l"(srcb + row * (IW * 4) + c16 * 16));
    }
    asm volatile("cp.async.commit_group;");

    // Zero row pads (x0=199 pair reads hit pad; lx=0 there so contributes 0).
    if (tid < 101) {
        float4* pad = (float4*)(smem + tid * (PITCH * 4) + IW * 4);
        *pad = make_float4(0.f, 0.f, 0.f, 0.f);
    }

    // ---- Copy this image's x-tables and this half's entry list ----
    const int nbs = d_nbox[img];
    const int ne  = d_nent[img * 2 + h];
    for (int t = tid; t < nbs * CROP; t += TPB)
        xtab[t] = d_xtab[img * MAXBI * CROP + t];
    for (int t = tid; t < ne; t += TPB)
        ents[t] = d_ent[(img * 2 + h) * MAXE + t];

    asm volatile("cp.async.wait_group 0;");
    __syncthreads();

    // ---- Gather: thread = (entry-group, col); zero wasted iterations ----
    const int e0  = tid / CROP;          // 0..63
    const int col = tid - e0 * CROP;     // 0..13
    float* outb = out + (size_t)ch * POS + col;

    #pragma unroll 2
    for (int e = e0; e < ne; e += EGRP) {
        const uint2 E = ents[e];
        const unsigned nid  = E.x & 511u;
        const unsigned slot = (E.x >> 9) & 255u;
        const int      o    = (E.x >> 17) & 127;
        const unsigned dy   = (E.x >> 24) & 1u;
        const unsigned vyr  = E.x >> 25;             // vy | r<<1
        const float    ly   = __uint_as_float(E.y);

        const uint2 tx = xtab[slot * CROP + col];
        const int   x0 = tx.x & 255;
        const float lx = __uint_as_float(tx.y);

        const float* r0 = plane + o * PITCH + x0;
        const float* r1 = r0 + dy * PITCH;
        const float tl = r0[0], tr = r0[1];
        const float bl = r1[0], br = r1[1];
        const float top = fmaf(tr - tl, lx, tl);
        const float bot = fmaf(br - bl, lx, bl);
        float val = fmaf(bot - top, ly, top);
        if (!(vyr & (tx.x >> 8) & 1u)) val = 0.0f;

        __stcs(outb + (size_t)nid * (NCH * POS) + (vyr >> 1) * CROP, val);
    }
}

extern "C" void kernel_launch(void* const* d_in, const int* in_sizes, int n_in,
                              void* d_out, int out_size)
{
    const float* image   = (const float*)d_in[0];
    const float* boxes   = (const float*)d_in[1];
    const int*   box_idx = (const int*)d_in[2];
    float*       out     = (float*)d_out;

    static bool attr_set = false;
    if (!attr_set) {
        cudaFuncSetAttribute(crop_resize_kernel,
                             cudaFuncAttributeMaxDynamicSharedMemorySize,
                             SM_TOTAL);
        attr_set = true;
    }

    prep_kernel<<<1, NBOX>>>(boxes, box_idx);
    crop_resize_kernel<<<NIMG * NCH * 2, TPB, SM_TOTAL>>>(image, out);
}